// round 14
// baseline (speedup 1.0000x reference)
#include <cuda_runtime.h>
#include <math.h>

// ---------------------------------------------------------------------------
// Categorical 2D semantic map: 16 frames, trilinear splat -> round -> z-sum.
//
//   1) scatter_kernel: per (frame, ds-pixel) computes trilinear corners.
//        - c0 occupancy: scalar atomicAdd into g_c0[f][z][col]
//        - sem channels: float4 atomicAdd into g_sem[f][zr][col][c/4],
//          processed in two 8-channel halves to cut register pressure.
//      Input loads use __ldcs (streaming/evict-first).
//      256-thread blocks over flattened pixels for occupancy/wave shape.
//   2) reduce_kernel: dense coalesced sweep, two uniform work classes:
//        - c0 class: thread per 4 columns (float4), 80 z-levels
//        - sem class: thread per (column, float4-quad), 17 z-levels
//      Zeroes every nonzero cell it reads (scratch stays clean across graph
//      replays -> no memset pass needed).
// ---------------------------------------------------------------------------

#define H2 120          // 480 / 4
#define W2 160          // 640 / 4
#define VR 100          // VISION_RANGE
#define ZL 80           // Z_LEVELS
#define ZAG_LO 8        // MIN_MAPPED_H
#define ZAG_HI 25       // MAX_MAPPED_H
#define ZAG_N  17
#define NSEM 16
#define NFRAMES 16
#define CH_ELEMS (480 * 640)
#define FRAME_ELEMS (20 * CH_ELEMS)
#define MAPC (VR * VR)

#define SCAT_BLOCKS 75  // 75*256 = 19200 pixels per frame
#define C0_BLOCKS  10   // 10*256 = 2560 >= 2500 float4-columns
#define SEM_BLOCKS 157  // 157*256 = 40192 >= 40000 (column, quad) items

// Zero-initialized at load; reduce_kernel restores zeros each call.
__device__ float g_c0[NFRAMES * ZL * MAPC];                        // [f][z][col]
__device__ float4 g_sem[(size_t)NFRAMES * ZAG_N * MAPC * 4];       // [f][zr][col][c/4]

__global__ void __launch_bounds__(256) scatter_kernel(const float* __restrict__ obs,
                                                      const float f_pix) {
    const int px = blockIdx.x * 256 + threadIdx.x;   // 0..19199
    const int j = px % W2;       // ds col
    const int i = px / W2;       // ds row
    const int f = blockIdx.y;    // frame

    const float* frame = obs + (size_t)f * FRAME_ELEMS;
    const float Yd = __ldcs(frame + 3 * CH_ELEMS + (4 * i) * 640 + 4 * j);
    if (!(Yd > 20.0f && Yd < 500.0f)) return;

    // Exact float op sequence of the reference.
    const float X  = ((float)(4 * j) - 319.5f) * Yd / f_pix;
    const float Z  = (239.5f - (float)(4 * i)) * Yd / f_pix;
    const float xm = X + 250.0f;
    const float zm = Z + 88.0f;
    const float xn = (xm / 5.0f - 50.0f) / 100.0f * 2.0f;
    const float yn = (Yd / 5.0f - 50.0f) / 100.0f * 2.0f;
    const float zn = (zm / 5.0f - 32.0f) / 80.0f * 2.0f;
    const float posx = xn * 50.0f + 50.0f;
    const float posy = yn * 50.0f + 50.0f;
    const float posz = zn * 40.0f + 40.0f;

    const float bxf = floorf(posx), byf = floorf(posy), bzf = floorf(posz);
    float wx[2], wy[2], wz[2];
#pragma unroll
    for (int t = 0; t < 2; t++) {
        float p;
        p = bxf + (float)t; wx[t] = (p > 0.0f && p < (float)VR) ? (1.0f - fabsf(posx - p)) : 0.0f;
        p = byf + (float)t; wy[t] = (p > 0.0f && p < (float)VR) ? (1.0f - fabsf(posy - p)) : 0.0f;
        p = bzf + (float)t; wz[t] = (p > 0.0f && p < (float)ZL) ? (1.0f - fabsf(posz - p)) : 0.0f;
    }
    if ((wx[0] == 0.0f && wx[1] == 0.0f) ||
        (wy[0] == 0.0f && wy[1] == 0.0f) ||
        (wz[0] == 0.0f && wz[1] == 0.0f)) return;

    const int xb = (int)bxf, yb = (int)byf, zb = (int)bzf;

    // Compact (x,y) corner list: offsets + quad weights.
    int   coff[4];
    float cw[4];
    int nc = 0;
#pragma unroll
    for (int tx = 0; tx < 2; tx++) {
        if (wx[tx] == 0.0f) continue;
#pragma unroll
        for (int ty = 0; ty < 2; ty++) {
            const float wq = wx[tx] * wy[ty];
            if (wq > 0.0f) { coff[nc] = (xb + tx) * VR + (yb + ty); cw[nc] = wq; nc++; }
        }
    }

    // --- channel 0 (occupancy): all z levels ---
    float* c0f = g_c0 + f * (ZL * MAPC);
    for (int k = 0; k < nc; k++) {
        if (wz[0] != 0.0f) atomicAdd(c0f + zb * MAPC + coff[k], cw[k] * wz[0]);
        if (wz[1] != 0.0f) atomicAdd(c0f + (zb + 1) * MAPC + coff[k], cw[k] * wz[1]);
    }

    // Sem channels matter only for z in [8,25): gate the pooled loads.
    const bool semz0 = (wz[0] != 0.0f) && (zb >= ZAG_LO) && (zb < ZAG_HI);
    const bool semz1 = (wz[1] != 0.0f) && (zb + 1 >= ZAG_LO) && (zb + 1 < ZAG_HI);
    if (!(semz0 || semz1)) return;

    const float* sbase = frame + 4 * CH_ELEMS + (4 * i) * 640 + 4 * j;
    float4* semf = g_sem + (size_t)f * (ZAG_N * MAPC) * 4;

    // Two 8-channel halves keep register pressure low.
#pragma unroll
    for (int h = 0; h < 2; h++) {
        float sem[8];
#pragma unroll
        for (int c = 0; c < 8; c++) {
            const float* cp = sbase + (h * 8 + c) * CH_ELEMS;
            float s = 0.0f;
#pragma unroll
            for (int r = 0; r < 4; r++) {
                float4 v = __ldcs(reinterpret_cast<const float4*>(cp + r * 640));
                s += v.x + v.y + v.z + v.w;
            }
            sem[c] = s * 0.0625f;
        }

#pragma unroll
        for (int tz = 0; tz < 2; tz++) {
            if (!(tz == 0 ? semz0 : semz1)) continue;
            const int zr = zb + tz - ZAG_LO;
            for (int k = 0; k < nc; k++) {
                const float w = cw[k] * wz[tz];
                float4* cell = semf + ((size_t)zr * MAPC + coff[k]) * 4 + h * 2;
                atomicAdd(cell + 0, make_float4(sem[0] * w, sem[1] * w, sem[2] * w, sem[3] * w));
                atomicAdd(cell + 1, make_float4(sem[4] * w, sem[5] * w, sem[6] * w, sem[7] * w));
            }
        }
    }
}

// grid = (C0_BLOCKS + SEM_BLOCKS, NFRAMES), block = 256.
__global__ void __launch_bounds__(256) reduce_kernel(float* __restrict__ out) {
    const int f = blockIdx.y;
    float* o = out + (size_t)f * 18 * MAPC;

    if (blockIdx.x < C0_BLOCKS) {
        // ---- c0 class: one thread per 4 columns (float4), 80 z-levels ----
        const int col4 = blockIdx.x * 256 + threadIdx.x;
        if (col4 >= MAPC / 4) return;
        float4* c0col = reinterpret_cast<float4*>(g_c0 + (size_t)f * (ZL * MAPC)) + col4;
        float4 s_all = make_float4(0.f, 0.f, 0.f, 0.f);
        float4 s_ag  = make_float4(0.f, 0.f, 0.f, 0.f);
        const float4 zf = make_float4(0.f, 0.f, 0.f, 0.f);
#pragma unroll 16
        for (int z = 0; z < ZL; z++) {
            const float4 v = c0col[(size_t)z * (MAPC / 4)];
            const float rx = rintf(v.x), ry = rintf(v.y), rz = rintf(v.z), rw = rintf(v.w);
            s_all.x += rx; s_all.y += ry; s_all.z += rz; s_all.w += rw;
            if (z >= ZAG_LO && z < ZAG_HI) {
                s_ag.x += rx; s_ag.y += ry; s_ag.z += rz; s_ag.w += rw;
            }
            if (v.x != 0.0f || v.y != 0.0f || v.z != 0.0f || v.w != 0.0f)
                c0col[(size_t)z * (MAPC / 4)] = zf;      // restore scratch
        }
        float4 m, e;
        m.x = fminf(fmaxf(s_ag.x, 0.f), 1.f); m.y = fminf(fmaxf(s_ag.y, 0.f), 1.f);
        m.z = fminf(fmaxf(s_ag.z, 0.f), 1.f); m.w = fminf(fmaxf(s_ag.w, 0.f), 1.f);
        e.x = fminf(fmaxf(s_all.x, 0.f), 1.f); e.y = fminf(fmaxf(s_all.y, 0.f), 1.f);
        e.z = fminf(fmaxf(s_all.z, 0.f), 1.f); e.w = fminf(fmaxf(s_all.w, 0.f), 1.f);
        reinterpret_cast<float4*>(o)[col4]            = m;   // fp_map (/1.0)
        reinterpret_cast<float4*>(o + MAPC)[col4]     = e;   // fp_exp (/1.0)
    } else {
        // ---- sem class: one thread per (column, float4-quad) ----
        const int item = (blockIdx.x - C0_BLOCKS) * 256 + threadIdx.x;
        if (item >= MAPC * 4) return;
        const int q = item & 3;           // which float4 (channels 4q..4q+3)
        const int col = item >> 2;
        float4* cell = g_sem + ((size_t)f * (ZAG_N * MAPC) + col) * 4 + q;
        float a0 = 0.0f, a1 = 0.0f, a2 = 0.0f, a3 = 0.0f;
        const float4 zf = make_float4(0.0f, 0.0f, 0.0f, 0.0f);
#pragma unroll
        for (int zr = 0; zr < ZAG_N; zr++) {
            const float4 v = cell[(size_t)zr * MAPC * 4];
            a0 += rintf(v.x); a1 += rintf(v.y); a2 += rintf(v.z); a3 += rintf(v.w);
            if (v.x != 0.0f || v.y != 0.0f || v.z != 0.0f || v.w != 0.0f)
                cell[(size_t)zr * MAPC * 4] = zf;    // restore scratch
        }
        const int c = 4 * q;
        o[(2 + c + 0) * MAPC + col] = fminf(fmaxf(a0 / 5.0f, 0.0f), 1.0f);
        o[(2 + c + 1) * MAPC + col] = fminf(fmaxf(a1 / 5.0f, 0.0f), 1.0f);
        o[(2 + c + 2) * MAPC + col] = fminf(fmaxf(a2 / 5.0f, 0.0f), 1.0f);
        o[(2 + c + 3) * MAPC + col] = fminf(fmaxf(a3 / 5.0f, 0.0f), 1.0f);
    }
}

extern "C" void kernel_launch(void* const* d_in, const int* in_sizes, int n_in,
                              void* d_out, int out_size) {
    const float* obs = (const float*)d_in[0];
    float* out = (float*)d_out;
    (void)in_sizes; (void)n_in; (void)out_size;

    // F_PIX computed in double (as numpy does), then narrowed to float32.
    const float f_pix = (float)(320.0 / tan(39.5 * 3.14159265358979323846 / 180.0));

    scatter_kernel<<<dim3(SCAT_BLOCKS, NFRAMES), 256>>>(obs, f_pix);
    reduce_kernel<<<dim3(C0_BLOCKS + SEM_BLOCKS, NFRAMES), 256>>>(out);
}

// round 15
// speedup vs baseline: 1.1253x; 1.1253x over previous
#include <cuda_runtime.h>
#include <math.h>

// ---------------------------------------------------------------------------
// Categorical 2D semantic map: 16 frames, trilinear splat -> round -> z-sum.
//
//   1) scatter_kernel (two-phase, smem compaction):
//        Phase 1: per ds-pixel geometry; c0 occupancy scalar atomicAdds into
//                 g_c0[f][z][col]; sem-active pixels (~18%) push a record
//                 into a shared-memory queue.
//        Phase 2: 4 threads per queued record (thread q = channel quad q):
//                 dense 4x4 pooling loads with FULL warp lane activity, then
//                 float4 atomicAdds into g_sem[f][zr][col][c/4].
//      Input loads use __ldcs (streaming/evict-first).
//   2) reduce_kernel (R8, unchanged): dense coalesced sweep, two uniform
//      work classes split by block index:
//        - c0 class: thread per column, 80 coalesced loads -> 2 outputs
//        - sem class: thread per (column, quad), 17 coalesced float4 loads
//      Zeroes every nonzero cell it reads (scratch stays clean across graph
//      replays -> no memset pass needed).
// ---------------------------------------------------------------------------

#define H2 120          // 480 / 4
#define W2 160          // 640 / 4
#define VR 100          // VISION_RANGE
#define ZL 80           // Z_LEVELS
#define ZAG_LO 8        // MIN_MAPPED_H
#define ZAG_HI 25       // MAX_MAPPED_H
#define ZAG_N  17
#define NSEM 16
#define NFRAMES 16
#define CH_ELEMS (480 * 640)
#define FRAME_ELEMS (20 * CH_ELEMS)
#define MAPC (VR * VR)

#define SCAT_BLOCKS 75  // 75*256 = 19200 pixels per frame
#define C0_BLOCKS  40   // 40*256 = 10240 >= 10000 columns
#define SEM_BLOCKS 157  // 157*256 = 40192 >= 40000 (column, quad) items

// Zero-initialized at load; reduce_kernel restores zeros each call.
__device__ float g_c0[NFRAMES * ZL * MAPC];                        // [f][z][col]
__device__ float4 g_sem[(size_t)NFRAMES * ZAG_N * MAPC * 4];       // [f][zr][col][c/4]

struct SemRec {
    float4 wq;          // corner weights wx*wy for (dx,dy) in {0,1}x{0,1}; 0 = skip
    float  wz0, wz1;    // z-direction weights
    int    pixoff;      // (4i)*640 + 4j into a channel plane
    int    off;         // xb*VR + yb  (corner cells at off + {0,1,VR,VR+1})
    int    zr0, zr1;    // z - ZAG_LO, or -1 if outside agent band / weight 0
};

__global__ void __launch_bounds__(256) scatter_kernel(const float* __restrict__ obs,
                                                      const float f_pix) {
    __shared__ int qcount;
    __shared__ SemRec q[256];

    const int px = blockIdx.x * 256 + threadIdx.x;   // 0..19199
    const int j = px % W2;       // ds col
    const int i = px / W2;       // ds row
    const int f = blockIdx.y;    // frame
    const float* frame = obs + (size_t)f * FRAME_ELEMS;

    if (threadIdx.x == 0) qcount = 0;
    __syncthreads();

    // ---------------- Phase 1: geometry + c0 + queue push ----------------
    const float Yd = __ldcs(frame + 3 * CH_ELEMS + (4 * i) * 640 + 4 * j);
    if (Yd > 20.0f && Yd < 500.0f) {
        // Exact float op sequence of the reference.
        const float X  = ((float)(4 * j) - 319.5f) * Yd / f_pix;
        const float Z  = (239.5f - (float)(4 * i)) * Yd / f_pix;
        const float xm = X + 250.0f;
        const float zm = Z + 88.0f;
        const float xn = (xm / 5.0f - 50.0f) / 100.0f * 2.0f;
        const float yn = (Yd / 5.0f - 50.0f) / 100.0f * 2.0f;
        const float zn = (zm / 5.0f - 32.0f) / 80.0f * 2.0f;
        const float posx = xn * 50.0f + 50.0f;
        const float posy = yn * 50.0f + 50.0f;
        const float posz = zn * 40.0f + 40.0f;

        const float bxf = floorf(posx), byf = floorf(posy), bzf = floorf(posz);
        float wx[2], wy[2], wz[2];
#pragma unroll
        for (int t = 0; t < 2; t++) {
            float p;
            p = bxf + (float)t; wx[t] = (p > 0.0f && p < (float)VR) ? (1.0f - fabsf(posx - p)) : 0.0f;
            p = byf + (float)t; wy[t] = (p > 0.0f && p < (float)VR) ? (1.0f - fabsf(posy - p)) : 0.0f;
            p = bzf + (float)t; wz[t] = (p > 0.0f && p < (float)ZL) ? (1.0f - fabsf(posz - p)) : 0.0f;
        }
        const bool any =
            !((wx[0] == 0.0f && wx[1] == 0.0f) ||
              (wy[0] == 0.0f && wy[1] == 0.0f) ||
              (wz[0] == 0.0f && wz[1] == 0.0f));

        if (any) {
            const int xb = (int)bxf, yb = (int)byf, zb = (int)bzf;
            const int off = xb * VR + yb;
            const float w00 = wx[0] * wy[0];
            const float w01 = wx[0] * wy[1];
            const float w10 = wx[1] * wy[0];
            const float w11 = wx[1] * wy[1];

            // --- channel 0 (occupancy): all z levels, scalar atomics ---
            float* c0f = g_c0 + f * (ZL * MAPC);
            if (wz[0] != 0.0f) {
                float* p0 = c0f + zb * MAPC + off;
                if (w00 > 0.0f) atomicAdd(p0,          w00 * wz[0]);
                if (w01 > 0.0f) atomicAdd(p0 + 1,      w01 * wz[0]);
                if (w10 > 0.0f) atomicAdd(p0 + VR,     w10 * wz[0]);
                if (w11 > 0.0f) atomicAdd(p0 + VR + 1, w11 * wz[0]);
            }
            if (wz[1] != 0.0f) {
                float* p1 = c0f + (zb + 1) * MAPC + off;
                if (w00 > 0.0f) atomicAdd(p1,          w00 * wz[1]);
                if (w01 > 0.0f) atomicAdd(p1 + 1,      w01 * wz[1]);
                if (w10 > 0.0f) atomicAdd(p1 + VR,     w10 * wz[1]);
                if (w11 > 0.0f) atomicAdd(p1 + VR + 1, w11 * wz[1]);
            }

            // Sem matters only for z in [8,25): push a compact record.
            const bool semz0 = (wz[0] != 0.0f) && (zb >= ZAG_LO) && (zb < ZAG_HI);
            const bool semz1 = (wz[1] != 0.0f) && (zb + 1 >= ZAG_LO) && (zb + 1 < ZAG_HI);
            if (semz0 || semz1) {
                const int idx = atomicAdd(&qcount, 1);
                SemRec rec;
                rec.wq = make_float4(w00, w01, w10, w11);
                rec.wz0 = wz[0];
                rec.wz1 = wz[1];
                rec.pixoff = (4 * i) * 640 + 4 * j;
                rec.off = off;
                rec.zr0 = semz0 ? (zb - ZAG_LO) : -1;
                rec.zr1 = semz1 ? (zb + 1 - ZAG_LO) : -1;
                q[idx] = rec;
            }
        }
    }
    __syncthreads();

    // ---------------- Phase 2: dense sem pooling + atomics ----------------
    const int cnt = qcount;
    float4* semf = g_sem + (size_t)f * (ZAG_N * MAPC) * 4;

    for (int base = 0; base < cnt; base += 64) {
        const int r = base + (threadIdx.x >> 2);
        if (r >= cnt) break;
        const int qd = threadIdx.x & 3;            // channel quad 0..3
        const SemRec rec = q[r];

        // Pool 4 channels (4*qd .. 4*qd+3), 4x4 window each, in two 2-channel
        // waves (8 outstanding loads per wave keeps registers moderate).
        const float* cp0 = frame + (4 + 4 * qd) * CH_ELEMS + rec.pixoff;
        float s[4];
#pragma unroll
        for (int hv = 0; hv < 2; hv++) {
            float4 v[8];
#pragma unroll
            for (int c = 0; c < 2; c++)
#pragma unroll
                for (int rr = 0; rr < 4; rr++)
                    v[c * 4 + rr] = __ldcs(reinterpret_cast<const float4*>(
                        cp0 + (hv * 2 + c) * CH_ELEMS + rr * 640));
#pragma unroll
            for (int c = 0; c < 2; c++) {
                float t = 0.0f;
#pragma unroll
                for (int rr = 0; rr < 4; rr++) {
                    const float4 x = v[c * 4 + rr];
                    t += x.x + x.y + x.z + x.w;
                }
                s[hv * 2 + c] = t * 0.0625f;
            }
        }

        const float cw[4] = { rec.wq.x, rec.wq.y, rec.wq.z, rec.wq.w };
        const int   dk[4] = { 0, 1, VR, VR + 1 };
#pragma unroll
        for (int tz = 0; tz < 2; tz++) {
            const int zr = tz ? rec.zr1 : rec.zr0;
            if (zr < 0) continue;
            const float wzv = tz ? rec.wz1 : rec.wz0;
            float4* plane = semf + (size_t)zr * MAPC * 4 + qd;
#pragma unroll
            for (int k = 0; k < 4; k++) {
                const float w = cw[k] * wzv;
                if (w > 0.0f)
                    atomicAdd(plane + (size_t)(rec.off + dk[k]) * 4,
                              make_float4(s[0] * w, s[1] * w, s[2] * w, s[3] * w));
            }
        }
    }
}

// grid = (C0_BLOCKS + SEM_BLOCKS, NFRAMES), block = 256.  (R8, unchanged)
__global__ void __launch_bounds__(256) reduce_kernel(float* __restrict__ out) {
    const int f = blockIdx.y;
    float* o = out + (size_t)f * 18 * MAPC;

    if (blockIdx.x < C0_BLOCKS) {
        // ---- c0 class: one thread per column, 80 z-levels ----
        const int col = blockIdx.x * 256 + threadIdx.x;
        if (col >= MAPC) return;
        float* c0col = g_c0 + (size_t)f * (ZL * MAPC) + col;
        float s_all = 0.0f, s_ag = 0.0f;
#pragma unroll 20
        for (int z = 0; z < ZL; z++) {
            const float v = c0col[(size_t)z * MAPC];
            if (v != 0.0f) {
                c0col[(size_t)z * MAPC] = 0.0f;      // restore scratch for next replay
                const float r = rintf(v);            // jnp.round = half-to-even
                s_all += r;
                if (z >= ZAG_LO && z < ZAG_HI) s_ag += r;
            }
        }
        o[col]        = fminf(fmaxf(s_ag,  0.0f), 1.0f);   // fp_map (/1.0)
        o[MAPC + col] = fminf(fmaxf(s_all, 0.0f), 1.0f);   // fp_exp (/1.0)
    } else {
        // ---- sem class: one thread per (column, float4-quad) ----
        const int item = (blockIdx.x - C0_BLOCKS) * 256 + threadIdx.x;
        if (item >= MAPC * 4) return;
        const int q = item & 3;           // which float4 (channels 4q..4q+3)
        const int col = item >> 2;
        float4* cell = g_sem + ((size_t)f * (ZAG_N * MAPC) + col) * 4 + q;
        float a0 = 0.0f, a1 = 0.0f, a2 = 0.0f, a3 = 0.0f;
        const float4 zf = make_float4(0.0f, 0.0f, 0.0f, 0.0f);
#pragma unroll
        for (int zr = 0; zr < ZAG_N; zr++) {
            const float4 v = cell[(size_t)zr * MAPC * 4];
            a0 += rintf(v.x); a1 += rintf(v.y); a2 += rintf(v.z); a3 += rintf(v.w);
            if (v.x != 0.0f || v.y != 0.0f || v.z != 0.0f || v.w != 0.0f)
                cell[(size_t)zr * MAPC * 4] = zf;    // restore scratch
        }
        const int c = 4 * q;
        o[(2 + c + 0) * MAPC + col] = fminf(fmaxf(a0 / 5.0f, 0.0f), 1.0f);
        o[(2 + c + 1) * MAPC + col] = fminf(fmaxf(a1 / 5.0f, 0.0f), 1.0f);
        o[(2 + c + 2) * MAPC + col] = fminf(fmaxf(a2 / 5.0f, 0.0f), 1.0f);
        o[(2 + c + 3) * MAPC + col] = fminf(fmaxf(a3 / 5.0f, 0.0f), 1.0f);
    }
}

extern "C" void kernel_launch(void* const* d_in, const int* in_sizes, int n_in,
                              void* d_out, int out_size) {
    const float* obs = (const float*)d_in[0];
    float* out = (float*)d_out;
    (void)in_sizes; (void)n_in; (void)out_size;

    // F_PIX computed in double (as numpy does), then narrowed to float32.
    const float f_pix = (float)(320.0 / tan(39.5 * 3.14159265358979323846 / 180.0));

    scatter_kernel<<<dim3(SCAT_BLOCKS, NFRAMES), 256>>>(obs, f_pix);
    reduce_kernel<<<dim3(C0_BLOCKS + SEM_BLOCKS, NFRAMES), 256>>>(out);
}

// round 16
// speedup vs baseline: 1.1343x; 1.0080x over previous
#include <cuda_runtime.h>
#include <math.h>

// ---------------------------------------------------------------------------
// Categorical 2D semantic map: 16 frames, trilinear splat -> round -> z-sum.
//
//   1) scatter_kernel (two-phase, smem compaction):
//        Phase 1: per ds-pixel geometry; c0 occupancy scalar atomicAdds into
//                 g_c0[f][z][col]; sem-active pixels (~18%) push a record
//                 into a shared-memory queue.
//        Phase 2: 4 threads per queued record (thread q = channel quad q):
//                 dense 4x4 pooling loads with FULL warp lane activity, then
//                 float4 atomicAdds into g_sem[f][zr][col][c/4].
//      Input loads use __ldcs (streaming/evict-first).
//   2) reduce_kernel (R8, unchanged): dense coalesced sweep, two uniform
//      work classes split by block index:
//        - c0 class: thread per column, 80 coalesced loads -> 2 outputs
//        - sem class: thread per (column, quad), 17 coalesced float4 loads
//      Zeroes every nonzero cell it reads (scratch stays clean across graph
//      replays -> no memset pass needed).
// ---------------------------------------------------------------------------

#define H2 120          // 480 / 4
#define W2 160          // 640 / 4
#define VR 100          // VISION_RANGE
#define ZL 80           // Z_LEVELS
#define ZAG_LO 8        // MIN_MAPPED_H
#define ZAG_HI 25       // MAX_MAPPED_H
#define ZAG_N  17
#define NSEM 16
#define NFRAMES 16
#define CH_ELEMS (480 * 640)
#define FRAME_ELEMS (20 * CH_ELEMS)
#define MAPC (VR * VR)

#define SCAT_BLOCKS 75  // 75*256 = 19200 pixels per frame
#define C0_BLOCKS  40   // 40*256 = 10240 >= 10000 columns
#define SEM_BLOCKS 157  // 157*256 = 40192 >= 40000 (column, quad) items

// Zero-initialized at load; reduce_kernel restores zeros each call.
__device__ float g_c0[NFRAMES * ZL * MAPC];                        // [f][z][col]
__device__ float4 g_sem[(size_t)NFRAMES * ZAG_N * MAPC * 4];       // [f][zr][col][c/4]

struct SemRec {
    float4 wq;          // corner weights wx*wy for (dx,dy) in {0,1}x{0,1}; 0 = skip
    float  wz0, wz1;    // z-direction weights
    int    pixoff;      // (4i)*640 + 4j into a channel plane
    int    off;         // xb*VR + yb  (corner cells at off + {0,1,VR,VR+1})
    int    zr0, zr1;    // z - ZAG_LO, or -1 if outside agent band / weight 0
};

__global__ void __launch_bounds__(256) scatter_kernel(const float* __restrict__ obs,
                                                      const float f_pix) {
    __shared__ int qcount;
    __shared__ SemRec q[256];

    const int px = blockIdx.x * 256 + threadIdx.x;   // 0..19199
    const int j = px % W2;       // ds col
    const int i = px / W2;       // ds row
    const int f = blockIdx.y;    // frame
    const float* frame = obs + (size_t)f * FRAME_ELEMS;

    if (threadIdx.x == 0) qcount = 0;
    __syncthreads();

    // ---------------- Phase 1: geometry + c0 + queue push ----------------
    const float Yd = __ldcs(frame + 3 * CH_ELEMS + (4 * i) * 640 + 4 * j);
    if (Yd > 20.0f && Yd < 500.0f) {
        // Exact float op sequence of the reference.
        const float X  = ((float)(4 * j) - 319.5f) * Yd / f_pix;
        const float Z  = (239.5f - (float)(4 * i)) * Yd / f_pix;
        const float xm = X + 250.0f;
        const float zm = Z + 88.0f;
        const float xn = (xm / 5.0f - 50.0f) / 100.0f * 2.0f;
        const float yn = (Yd / 5.0f - 50.0f) / 100.0f * 2.0f;
        const float zn = (zm / 5.0f - 32.0f) / 80.0f * 2.0f;
        const float posx = xn * 50.0f + 50.0f;
        const float posy = yn * 50.0f + 50.0f;
        const float posz = zn * 40.0f + 40.0f;

        const float bxf = floorf(posx), byf = floorf(posy), bzf = floorf(posz);
        float wx[2], wy[2], wz[2];
#pragma unroll
        for (int t = 0; t < 2; t++) {
            float p;
            p = bxf + (float)t; wx[t] = (p > 0.0f && p < (float)VR) ? (1.0f - fabsf(posx - p)) : 0.0f;
            p = byf + (float)t; wy[t] = (p > 0.0f && p < (float)VR) ? (1.0f - fabsf(posy - p)) : 0.0f;
            p = bzf + (float)t; wz[t] = (p > 0.0f && p < (float)ZL) ? (1.0f - fabsf(posz - p)) : 0.0f;
        }
        const bool any =
            !((wx[0] == 0.0f && wx[1] == 0.0f) ||
              (wy[0] == 0.0f && wy[1] == 0.0f) ||
              (wz[0] == 0.0f && wz[1] == 0.0f));

        if (any) {
            const int xb = (int)bxf, yb = (int)byf, zb = (int)bzf;
            const int off = xb * VR + yb;
            const float w00 = wx[0] * wy[0];
            const float w01 = wx[0] * wy[1];
            const float w10 = wx[1] * wy[0];
            const float w11 = wx[1] * wy[1];

            // --- channel 0 (occupancy): all z levels, scalar atomics ---
            float* c0f = g_c0 + f * (ZL * MAPC);
            if (wz[0] != 0.0f) {
                float* p0 = c0f + zb * MAPC + off;
                if (w00 > 0.0f) atomicAdd(p0,          w00 * wz[0]);
                if (w01 > 0.0f) atomicAdd(p0 + 1,      w01 * wz[0]);
                if (w10 > 0.0f) atomicAdd(p0 + VR,     w10 * wz[0]);
                if (w11 > 0.0f) atomicAdd(p0 + VR + 1, w11 * wz[0]);
            }
            if (wz[1] != 0.0f) {
                float* p1 = c0f + (zb + 1) * MAPC + off;
                if (w00 > 0.0f) atomicAdd(p1,          w00 * wz[1]);
                if (w01 > 0.0f) atomicAdd(p1 + 1,      w01 * wz[1]);
                if (w10 > 0.0f) atomicAdd(p1 + VR,     w10 * wz[1]);
                if (w11 > 0.0f) atomicAdd(p1 + VR + 1, w11 * wz[1]);
            }

            // Sem matters only for z in [8,25): push a compact record.
            const bool semz0 = (wz[0] != 0.0f) && (zb >= ZAG_LO) && (zb < ZAG_HI);
            const bool semz1 = (wz[1] != 0.0f) && (zb + 1 >= ZAG_LO) && (zb + 1 < ZAG_HI);
            if (semz0 || semz1) {
                const int idx = atomicAdd(&qcount, 1);
                SemRec rec;
                rec.wq = make_float4(w00, w01, w10, w11);
                rec.wz0 = wz[0];
                rec.wz1 = wz[1];
                rec.pixoff = (4 * i) * 640 + 4 * j;
                rec.off = off;
                rec.zr0 = semz0 ? (zb - ZAG_LO) : -1;
                rec.zr1 = semz1 ? (zb + 1 - ZAG_LO) : -1;
                q[idx] = rec;
            }
        }
    }
    __syncthreads();

    // ---------------- Phase 2: dense sem pooling + atomics ----------------
    const int cnt = qcount;
    float4* semf = g_sem + (size_t)f * (ZAG_N * MAPC) * 4;

    for (int base = 0; base < cnt; base += 64) {
        const int r = base + (threadIdx.x >> 2);
        if (r >= cnt) break;
        const int qd = threadIdx.x & 3;            // channel quad 0..3
        const SemRec rec = q[r];

        // Pool 4 channels (4*qd .. 4*qd+3), 4x4 window each, in two 2-channel
        // waves (8 outstanding loads per wave keeps registers moderate).
        const float* cp0 = frame + (4 + 4 * qd) * CH_ELEMS + rec.pixoff;
        float s[4];
#pragma unroll
        for (int hv = 0; hv < 2; hv++) {
            float4 v[8];
#pragma unroll
            for (int c = 0; c < 2; c++)
#pragma unroll
                for (int rr = 0; rr < 4; rr++)
                    v[c * 4 + rr] = __ldcs(reinterpret_cast<const float4*>(
                        cp0 + (hv * 2 + c) * CH_ELEMS + rr * 640));
#pragma unroll
            for (int c = 0; c < 2; c++) {
                float t = 0.0f;
#pragma unroll
                for (int rr = 0; rr < 4; rr++) {
                    const float4 x = v[c * 4 + rr];
                    t += x.x + x.y + x.z + x.w;
                }
                s[hv * 2 + c] = t * 0.0625f;
            }
        }

        const float cw[4] = { rec.wq.x, rec.wq.y, rec.wq.z, rec.wq.w };
        const int   dk[4] = { 0, 1, VR, VR + 1 };
#pragma unroll
        for (int tz = 0; tz < 2; tz++) {
            const int zr = tz ? rec.zr1 : rec.zr0;
            if (zr < 0) continue;
            const float wzv = tz ? rec.wz1 : rec.wz0;
            float4* plane = semf + (size_t)zr * MAPC * 4 + qd;
#pragma unroll
            for (int k = 0; k < 4; k++) {
                const float w = cw[k] * wzv;
                if (w > 0.0f)
                    atomicAdd(plane + (size_t)(rec.off + dk[k]) * 4,
                              make_float4(s[0] * w, s[1] * w, s[2] * w, s[3] * w));
            }
        }
    }
}

// grid = (C0_BLOCKS + SEM_BLOCKS, NFRAMES), block = 256.  (R8, unchanged)
__global__ void __launch_bounds__(256) reduce_kernel(float* __restrict__ out) {
    const int f = blockIdx.y;
    float* o = out + (size_t)f * 18 * MAPC;

    if (blockIdx.x < C0_BLOCKS) {
        // ---- c0 class: one thread per column, 80 z-levels ----
        const int col = blockIdx.x * 256 + threadIdx.x;
        if (col >= MAPC) return;
        float* c0col = g_c0 + (size_t)f * (ZL * MAPC) + col;
        float s_all = 0.0f, s_ag = 0.0f;
#pragma unroll 20
        for (int z = 0; z < ZL; z++) {
            const float v = c0col[(size_t)z * MAPC];
            if (v != 0.0f) {
                c0col[(size_t)z * MAPC] = 0.0f;      // restore scratch for next replay
                const float r = rintf(v);            // jnp.round = half-to-even
                s_all += r;
                if (z >= ZAG_LO && z < ZAG_HI) s_ag += r;
            }
        }
        o[col]        = fminf(fmaxf(s_ag,  0.0f), 1.0f);   // fp_map (/1.0)
        o[MAPC + col] = fminf(fmaxf(s_all, 0.0f), 1.0f);   // fp_exp (/1.0)
    } else {
        // ---- sem class: one thread per (column, float4-quad) ----
        const int item = (blockIdx.x - C0_BLOCKS) * 256 + threadIdx.x;
        if (item >= MAPC * 4) return;
        const int q = item & 3;           // which float4 (channels 4q..4q+3)
        const int col = item >> 2;
        float4* cell = g_sem + ((size_t)f * (ZAG_N * MAPC) + col) * 4 + q;
        float a0 = 0.0f, a1 = 0.0f, a2 = 0.0f, a3 = 0.0f;
        const float4 zf = make_float4(0.0f, 0.0f, 0.0f, 0.0f);
#pragma unroll
        for (int zr = 0; zr < ZAG_N; zr++) {
            const float4 v = cell[(size_t)zr * MAPC * 4];
            a0 += rintf(v.x); a1 += rintf(v.y); a2 += rintf(v.z); a3 += rintf(v.w);
            if (v.x != 0.0f || v.y != 0.0f || v.z != 0.0f || v.w != 0.0f)
                cell[(size_t)zr * MAPC * 4] = zf;    // restore scratch
        }
        const int c = 4 * q;
        o[(2 + c + 0) * MAPC + col] = fminf(fmaxf(a0 / 5.0f, 0.0f), 1.0f);
        o[(2 + c + 1) * MAPC + col] = fminf(fmaxf(a1 / 5.0f, 0.0f), 1.0f);
        o[(2 + c + 2) * MAPC + col] = fminf(fmaxf(a2 / 5.0f, 0.0f), 1.0f);
        o[(2 + c + 3) * MAPC + col] = fminf(fmaxf(a3 / 5.0f, 0.0f), 1.0f);
    }
}

extern "C" void kernel_launch(void* const* d_in, const int* in_sizes, int n_in,
                              void* d_out, int out_size) {
    const float* obs = (const float*)d_in[0];
    float* out = (float*)d_out;
    (void)in_sizes; (void)n_in; (void)out_size;

    // F_PIX computed in double (as numpy does), then narrowed to float32.
    const float f_pix = (float)(320.0 / tan(39.5 * 3.14159265358979323846 / 180.0));

    scatter_kernel<<<dim3(SCAT_BLOCKS, NFRAMES), 256>>>(obs, f_pix);
    reduce_kernel<<<dim3(C0_BLOCKS + SEM_BLOCKS, NFRAMES), 256>>>(out);
}

// round 17
// speedup vs baseline: 1.1442x; 1.0088x over previous
#include <cuda_runtime.h>
#include <math.h>

// ---------------------------------------------------------------------------
// Categorical 2D semantic map: 16 frames, trilinear splat -> round -> z-sum.
//
//   1) scatter_kernel (two-phase, smem compaction):
//        Phase 1: per ds-pixel geometry; c0 occupancy scalar atomicAdds into
//                 g_c0[f][z][col]; sem-active pixels (~18%) push a record
//                 into a shared-memory queue.
//        Phase 2: 4 threads per queued record (thread q = channel quad q):
//                 dense 4x4 pooling loads with FULL warp lane activity, then
//                 float4 atomicAdds into g_sem[f][zr][col][c/4].
//      Input loads use __ldcs (streaming/evict-first).
//   2) reduce_kernel (R8, unchanged): dense coalesced sweep, two uniform
//      work classes split by block index:
//        - c0 class: thread per column, 80 coalesced loads -> 2 outputs
//        - sem class: thread per (column, quad), 17 coalesced float4 loads
//      Zeroes every nonzero cell it reads (scratch stays clean across graph
//      replays -> no memset pass needed).
// ---------------------------------------------------------------------------

#define H2 120          // 480 / 4
#define W2 160          // 640 / 4
#define VR 100          // VISION_RANGE
#define ZL 80           // Z_LEVELS
#define ZAG_LO 8        // MIN_MAPPED_H
#define ZAG_HI 25       // MAX_MAPPED_H
#define ZAG_N  17
#define NSEM 16
#define NFRAMES 16
#define CH_ELEMS (480 * 640)
#define FRAME_ELEMS (20 * CH_ELEMS)
#define MAPC (VR * VR)

#define SCAT_BLOCKS 75  // 75*256 = 19200 pixels per frame
#define C0_BLOCKS  40   // 40*256 = 10240 >= 10000 columns
#define SEM_BLOCKS 157  // 157*256 = 40192 >= 40000 (column, quad) items

// Zero-initialized at load; reduce_kernel restores zeros each call.
__device__ float g_c0[NFRAMES * ZL * MAPC];                        // [f][z][col]
__device__ float4 g_sem[(size_t)NFRAMES * ZAG_N * MAPC * 4];       // [f][zr][col][c/4]

struct SemRec {
    float4 wq;          // corner weights wx*wy for (dx,dy) in {0,1}x{0,1}; 0 = skip
    float  wz0, wz1;    // z-direction weights
    int    pixoff;      // (4i)*640 + 4j into a channel plane
    int    off;         // xb*VR + yb  (corner cells at off + {0,1,VR,VR+1})
    int    zr0, zr1;    // z - ZAG_LO, or -1 if outside agent band / weight 0
};

__global__ void __launch_bounds__(256) scatter_kernel(const float* __restrict__ obs,
                                                      const float f_pix) {
    __shared__ int qcount;
    __shared__ SemRec q[256];

    const int px = blockIdx.x * 256 + threadIdx.x;   // 0..19199
    const int j = px % W2;       // ds col
    const int i = px / W2;       // ds row
    const int f = blockIdx.y;    // frame
    const float* frame = obs + (size_t)f * FRAME_ELEMS;

    if (threadIdx.x == 0) qcount = 0;
    __syncthreads();

    // ---------------- Phase 1: geometry + c0 + queue push ----------------
    const float Yd = __ldcs(frame + 3 * CH_ELEMS + (4 * i) * 640 + 4 * j);
    if (Yd > 20.0f && Yd < 500.0f) {
        // Exact float op sequence of the reference.
        const float X  = ((float)(4 * j) - 319.5f) * Yd / f_pix;
        const float Z  = (239.5f - (float)(4 * i)) * Yd / f_pix;
        const float xm = X + 250.0f;
        const float zm = Z + 88.0f;
        const float xn = (xm / 5.0f - 50.0f) / 100.0f * 2.0f;
        const float yn = (Yd / 5.0f - 50.0f) / 100.0f * 2.0f;
        const float zn = (zm / 5.0f - 32.0f) / 80.0f * 2.0f;
        const float posx = xn * 50.0f + 50.0f;
        const float posy = yn * 50.0f + 50.0f;
        const float posz = zn * 40.0f + 40.0f;

        const float bxf = floorf(posx), byf = floorf(posy), bzf = floorf(posz);
        float wx[2], wy[2], wz[2];
#pragma unroll
        for (int t = 0; t < 2; t++) {
            float p;
            p = bxf + (float)t; wx[t] = (p > 0.0f && p < (float)VR) ? (1.0f - fabsf(posx - p)) : 0.0f;
            p = byf + (float)t; wy[t] = (p > 0.0f && p < (float)VR) ? (1.0f - fabsf(posy - p)) : 0.0f;
            p = bzf + (float)t; wz[t] = (p > 0.0f && p < (float)ZL) ? (1.0f - fabsf(posz - p)) : 0.0f;
        }
        const bool any =
            !((wx[0] == 0.0f && wx[1] == 0.0f) ||
              (wy[0] == 0.0f && wy[1] == 0.0f) ||
              (wz[0] == 0.0f && wz[1] == 0.0f));

        if (any) {
            const int xb = (int)bxf, yb = (int)byf, zb = (int)bzf;
            const int off = xb * VR + yb;
            const float w00 = wx[0] * wy[0];
            const float w01 = wx[0] * wy[1];
            const float w10 = wx[1] * wy[0];
            const float w11 = wx[1] * wy[1];

            // --- channel 0 (occupancy): all z levels, scalar atomics ---
            float* c0f = g_c0 + f * (ZL * MAPC);
            if (wz[0] != 0.0f) {
                float* p0 = c0f + zb * MAPC + off;
                if (w00 > 0.0f) atomicAdd(p0,          w00 * wz[0]);
                if (w01 > 0.0f) atomicAdd(p0 + 1,      w01 * wz[0]);
                if (w10 > 0.0f) atomicAdd(p0 + VR,     w10 * wz[0]);
                if (w11 > 0.0f) atomicAdd(p0 + VR + 1, w11 * wz[0]);
            }
            if (wz[1] != 0.0f) {
                float* p1 = c0f + (zb + 1) * MAPC + off;
                if (w00 > 0.0f) atomicAdd(p1,          w00 * wz[1]);
                if (w01 > 0.0f) atomicAdd(p1 + 1,      w01 * wz[1]);
                if (w10 > 0.0f) atomicAdd(p1 + VR,     w10 * wz[1]);
                if (w11 > 0.0f) atomicAdd(p1 + VR + 1, w11 * wz[1]);
            }

            // Sem matters only for z in [8,25): push a compact record.
            const bool semz0 = (wz[0] != 0.0f) && (zb >= ZAG_LO) && (zb < ZAG_HI);
            const bool semz1 = (wz[1] != 0.0f) && (zb + 1 >= ZAG_LO) && (zb + 1 < ZAG_HI);
            if (semz0 || semz1) {
                const int idx = atomicAdd(&qcount, 1);
                SemRec rec;
                rec.wq = make_float4(w00, w01, w10, w11);
                rec.wz0 = wz[0];
                rec.wz1 = wz[1];
                rec.pixoff = (4 * i) * 640 + 4 * j;
                rec.off = off;
                rec.zr0 = semz0 ? (zb - ZAG_LO) : -1;
                rec.zr1 = semz1 ? (zb + 1 - ZAG_LO) : -1;
                q[idx] = rec;
            }
        }
    }
    __syncthreads();

    // ---------------- Phase 2: dense sem pooling + atomics ----------------
    const int cnt = qcount;
    float4* semf = g_sem + (size_t)f * (ZAG_N * MAPC) * 4;

    for (int base = 0; base < cnt; base += 64) {
        const int r = base + (threadIdx.x >> 2);
        if (r >= cnt) break;
        const int qd = threadIdx.x & 3;            // channel quad 0..3
        const SemRec rec = q[r];

        // Pool 4 channels (4*qd .. 4*qd+3), 4x4 window each, in two 2-channel
        // waves (8 outstanding loads per wave keeps registers moderate).
        const float* cp0 = frame + (4 + 4 * qd) * CH_ELEMS + rec.pixoff;
        float s[4];
#pragma unroll
        for (int hv = 0; hv < 2; hv++) {
            float4 v[8];
#pragma unroll
            for (int c = 0; c < 2; c++)
#pragma unroll
                for (int rr = 0; rr < 4; rr++)
                    v[c * 4 + rr] = __ldcs(reinterpret_cast<const float4*>(
                        cp0 + (hv * 2 + c) * CH_ELEMS + rr * 640));
#pragma unroll
            for (int c = 0; c < 2; c++) {
                float t = 0.0f;
#pragma unroll
                for (int rr = 0; rr < 4; rr++) {
                    const float4 x = v[c * 4 + rr];
                    t += x.x + x.y + x.z + x.w;
                }
                s[hv * 2 + c] = t * 0.0625f;
            }
        }

        const float cw[4] = { rec.wq.x, rec.wq.y, rec.wq.z, rec.wq.w };
        const int   dk[4] = { 0, 1, VR, VR + 1 };
#pragma unroll
        for (int tz = 0; tz < 2; tz++) {
            const int zr = tz ? rec.zr1 : rec.zr0;
            if (zr < 0) continue;
            const float wzv = tz ? rec.wz1 : rec.wz0;
            float4* plane = semf + (size_t)zr * MAPC * 4 + qd;
#pragma unroll
            for (int k = 0; k < 4; k++) {
                const float w = cw[k] * wzv;
                if (w > 0.0f)
                    atomicAdd(plane + (size_t)(rec.off + dk[k]) * 4,
                              make_float4(s[0] * w, s[1] * w, s[2] * w, s[3] * w));
            }
        }
    }
}

// grid = (C0_BLOCKS + SEM_BLOCKS, NFRAMES), block = 256.  (R8, unchanged)
__global__ void __launch_bounds__(256) reduce_kernel(float* __restrict__ out) {
    const int f = blockIdx.y;
    float* o = out + (size_t)f * 18 * MAPC;

    if (blockIdx.x < C0_BLOCKS) {
        // ---- c0 class: one thread per column, 80 z-levels ----
        const int col = blockIdx.x * 256 + threadIdx.x;
        if (col >= MAPC) return;
        float* c0col = g_c0 + (size_t)f * (ZL * MAPC) + col;
        float s_all = 0.0f, s_ag = 0.0f;
#pragma unroll 20
        for (int z = 0; z < ZL; z++) {
            const float v = c0col[(size_t)z * MAPC];
            if (v != 0.0f) {
                c0col[(size_t)z * MAPC] = 0.0f;      // restore scratch for next replay
                const float r = rintf(v);            // jnp.round = half-to-even
                s_all += r;
                if (z >= ZAG_LO && z < ZAG_HI) s_ag += r;
            }
        }
        o[col]        = fminf(fmaxf(s_ag,  0.0f), 1.0f);   // fp_map (/1.0)
        o[MAPC + col] = fminf(fmaxf(s_all, 0.0f), 1.0f);   // fp_exp (/1.0)
    } else {
        // ---- sem class: one thread per (column, float4-quad) ----
        const int item = (blockIdx.x - C0_BLOCKS) * 256 + threadIdx.x;
        if (item >= MAPC * 4) return;
        const int q = item & 3;           // which float4 (channels 4q..4q+3)
        const int col = item >> 2;
        float4* cell = g_sem + ((size_t)f * (ZAG_N * MAPC) + col) * 4 + q;
        float a0 = 0.0f, a1 = 0.0f, a2 = 0.0f, a3 = 0.0f;
        const float4 zf = make_float4(0.0f, 0.0f, 0.0f, 0.0f);
#pragma unroll
        for (int zr = 0; zr < ZAG_N; zr++) {
            const float4 v = cell[(size_t)zr * MAPC * 4];
            a0 += rintf(v.x); a1 += rintf(v.y); a2 += rintf(v.z); a3 += rintf(v.w);
            if (v.x != 0.0f || v.y != 0.0f || v.z != 0.0f || v.w != 0.0f)
                cell[(size_t)zr * MAPC * 4] = zf;    // restore scratch
        }
        const int c = 4 * q;
        o[(2 + c + 0) * MAPC + col] = fminf(fmaxf(a0 / 5.0f, 0.0f), 1.0f);
        o[(2 + c + 1) * MAPC + col] = fminf(fmaxf(a1 / 5.0f, 0.0f), 1.0f);
        o[(2 + c + 2) * MAPC + col] = fminf(fmaxf(a2 / 5.0f, 0.0f), 1.0f);
        o[(2 + c + 3) * MAPC + col] = fminf(fmaxf(a3 / 5.0f, 0.0f), 1.0f);
    }
}

extern "C" void kernel_launch(void* const* d_in, const int* in_sizes, int n_in,
                              void* d_out, int out_size) {
    const float* obs = (const float*)d_in[0];
    float* out = (float*)d_out;
    (void)in_sizes; (void)n_in; (void)out_size;

    // F_PIX computed in double (as numpy does), then narrowed to float32.
    const float f_pix = (float)(320.0 / tan(39.5 * 3.14159265358979323846 / 180.0));

    scatter_kernel<<<dim3(SCAT_BLOCKS, NFRAMES), 256>>>(obs, f_pix);
    reduce_kernel<<<dim3(C0_BLOCKS + SEM_BLOCKS, NFRAMES), 256>>>(out);
}